// round 4
// baseline (speedup 1.0000x reference)
#include <cuda_runtime.h>
#include <math.h>
#include <stdint.h>

// ---------------- problem constants ----------------
#define BATCH 2
#define SEQ   2048
#define DM    5120
#define NH    8
#define DH    640
#define DR    16
#define SPLITD 624
#define DKV   128
#define MROWS (BATCH*SEQ)        // 4096
#define NCOMP (NH*SPLITD)        // 4992 = 39*128

// ---------------- scratch (device globals; no allocs allowed) ----------------
__device__ __align__(16) float g_ckv [MROWS*DKV];
__device__ __align__(16) float g_cq  [MROWS*DKV];
__device__ __align__(16) float g_qrot[MROWS*DKV];
__device__ __align__(16) float g_krot[MROWS*DKV];
__device__ __align__(16) float g_kbt [(size_t)MROWS*NCOMP];
__device__ __align__(16) float g_qbt [(size_t)MROWS*NCOMP];
__device__ __align__(16) float g_q   [(size_t)MROWS*DM];
__device__ __align__(16) float g_k   [(size_t)MROWS*DM];
__device__ __align__(16) float g_v   [(size_t)MROWS*DM];
__device__ __align__(16) float g_vt  [(size_t)MROWS*DM];
__device__ __align__(16) float g_ao  [(size_t)MROWS*DM];
__device__ __align__(16) float g_sc  [(size_t)BATCH*NH*SEQ*SEQ];   // 256 MB scores
// transposed weights (B operands must be [N,K] K-major), pre-rounded to tf32
__device__ __align__(16) float g_wt_dkv[DKV*DM];
__device__ __align__(16) float g_wt_dq [DKV*DM];
__device__ __align__(16) float g_wt_uk [NCOMP*DKV];
__device__ __align__(16) float g_wt_uq [NCOMP*DKV];
__device__ __align__(16) float g_wt_uv [DM*DKV];
__device__ __align__(16) float g_wt_kr [DKV*DKV];
__device__ __align__(16) float g_wt_qr [DKV*DKV];
__device__ __align__(16) float g_wt_out[(size_t)DM*DM];

// ---------------- small PTX helpers ----------------
__device__ __forceinline__ uint32_t smem_u32(const void* p) {
    uint32_t a;
    asm("{ .reg .u64 t; cvta.to.shared.u64 t, %1; cvt.u32.u64 %0, t; }" : "=r"(a) : "l"(p));
    return a;
}
__device__ __forceinline__ void cp16(uint32_t dst, const void* src) {
    asm volatile("cp.async.cg.shared.global [%0], [%1], 16;" :: "r"(dst), "l"(src) : "memory");
}
#define CP_COMMIT() asm volatile("cp.async.commit_group;" ::: "memory")
#define CP_WAIT(n)  asm volatile("cp.async.wait_group %0;" :: "n"(n) : "memory")

__device__ __forceinline__ uint32_t f2t(float x) {
    uint32_t r;
    asm("cvt.rna.tf32.f32 %0, %1;" : "=r"(r) : "f"(x));
    return r;
}
__device__ __forceinline__ float f2tf(float x) {       // tf32-round, keep as float
    return __uint_as_float(f2t(x));
}
__device__ __forceinline__ void mma_tf32(float* c, const uint32_t* a, uint32_t b0, uint32_t b1) {
    asm volatile("mma.sync.aligned.m16n8k8.row.col.f32.tf32.tf32.f32 "
                 "{%0,%1,%2,%3}, {%4,%5,%6,%7}, {%8,%9}, {%0,%1,%2,%3};"
                 : "+f"(c[0]), "+f"(c[1]), "+f"(c[2]), "+f"(c[3])
                 : "r"(a[0]), "r"(a[1]), "r"(a[2]), "r"(a[3]), "r"(b0), "r"(b1));
}

// ============================================================================
// tf32 mma.sync GEMM: C[M,N] = alpha * A[M,K] * B[N,K]^T (+ bias)
// M%128==0, N%128==0, K%16==0, 256 threads, double-buffered cp.async pipeline
// CVTA/CVTB: round fragments to tf32 on load (only needed for raw-fp32 inputs)
// CVTC: round C to tf32 on store (when C feeds a later GEMM as raw operand)
// ============================================================================
#define BKQ 16
#define SPAD 20    // BK + 4 pad, conflict-free for fragment loads

template<bool CVTA, bool CVTB, bool CVTC>
__global__ __launch_bounds__(256)
void mmagemm(const float* __restrict__ A, const float* __restrict__ B,
             float* __restrict__ C, const float* __restrict__ bias,
             int M, int N, int K, int lda, int ldb, int ldc, float alpha,
             long long sAhi, long long sAlo, long long sBhi, long long sBlo,
             long long sChi, long long sClo, int zdiv)
{
    __shared__ float As[2][128][SPAD];
    __shared__ float Bs[2][128][SPAD];

    int tid  = threadIdx.x;
    int warp = tid >> 5;
    int lane = tid & 31;
    int wr = warp >> 1;          // 0..3 warp row
    int wc = warp & 1;           // 0..1 warp col
    int qid = lane >> 2;         // 0..7
    int tig = lane & 3;          // 0..3

    int z  = blockIdx.z;
    int zh = z / zdiv, zl = z % zdiv;
    A += zh * sAhi + zl * sAlo;
    B += zh * sBhi + zl * sBlo;
    C += zh * sChi + zl * sClo;

    int row0 = blockIdx.y * 128, col0 = blockIdx.x * 128;
    const float* Ab = A + (size_t)row0 * lda;
    const float* Bb = B + (size_t)col0 * ldb;

    int lr0 = tid >> 2,           lc0 = (tid & 3) * 4;
    int lr1 = (tid + 256) >> 2,   lc1 = lc0;
    uint32_t sA0[2], sA1[2], sB0[2], sB1[2];
#pragma unroll
    for (int s = 0; s < 2; s++) {
        sA0[s] = smem_u32(&As[s][lr0][lc0]);
        sA1[s] = smem_u32(&As[s][lr1][lc1]);
        sB0[s] = smem_u32(&Bs[s][lr0][lc0]);
        sB1[s] = smem_u32(&Bs[s][lr1][lc1]);
    }

    float acc[2][8][4];
#pragma unroll
    for (int mi = 0; mi < 2; mi++)
#pragma unroll
        for (int ni = 0; ni < 8; ni++)
#pragma unroll
            for (int i = 0; i < 4; i++) acc[mi][ni][i] = 0.0f;

    int T = K / BKQ;

    // prologue: tile 0
    {
        cp16(sA0[0], Ab + (size_t)lr0 * lda + lc0);
        cp16(sA1[0], Ab + (size_t)lr1 * lda + lc1);
        cp16(sB0[0], Bb + (size_t)lr0 * ldb + lc0);
        cp16(sB1[0], Bb + (size_t)lr1 * ldb + lc1);
        CP_COMMIT();
    }

    for (int t = 0; t < T; t++) {
        if (t + 1 < T) {
            int s = (t + 1) & 1;
            int k0 = (t + 1) * BKQ;
            cp16(sA0[s], Ab + (size_t)lr0 * lda + k0 + lc0);
            cp16(sA1[s], Ab + (size_t)lr1 * lda + k0 + lc1);
            cp16(sB0[s], Bb + (size_t)lr0 * ldb + k0 + lc0);
            cp16(sB1[s], Bb + (size_t)lr1 * ldb + k0 + lc1);
            CP_COMMIT();
            CP_WAIT(1);
        } else {
            CP_WAIT(0);
        }
        __syncthreads();

        int s = t & 1;
#pragma unroll
        for (int ks = 0; ks < 2; ks++) {
            int k0 = ks * 8;
            uint32_t a[2][4];
#pragma unroll
            for (int mi = 0; mi < 2; mi++) {
                int rb = wr * 32 + mi * 16;
                if (CVTA) {
                    a[mi][0] = f2t(As[s][rb + qid    ][k0 + tig    ]);
                    a[mi][1] = f2t(As[s][rb + qid + 8][k0 + tig    ]);
                    a[mi][2] = f2t(As[s][rb + qid    ][k0 + tig + 4]);
                    a[mi][3] = f2t(As[s][rb + qid + 8][k0 + tig + 4]);
                } else {
                    a[mi][0] = __float_as_uint(As[s][rb + qid    ][k0 + tig    ]);
                    a[mi][1] = __float_as_uint(As[s][rb + qid + 8][k0 + tig    ]);
                    a[mi][2] = __float_as_uint(As[s][rb + qid    ][k0 + tig + 4]);
                    a[mi][3] = __float_as_uint(As[s][rb + qid + 8][k0 + tig + 4]);
                }
            }
#pragma unroll
            for (int ni = 0; ni < 8; ni++) {
                int cb = wc * 64 + ni * 8;
                uint32_t b0, b1;
                if (CVTB) {
                    b0 = f2t(Bs[s][cb + qid][k0 + tig    ]);
                    b1 = f2t(Bs[s][cb + qid][k0 + tig + 4]);
                } else {
                    b0 = __float_as_uint(Bs[s][cb + qid][k0 + tig    ]);
                    b1 = __float_as_uint(Bs[s][cb + qid][k0 + tig + 4]);
                }
                mma_tf32(acc[0][ni], a[0], b0, b1);
                mma_tf32(acc[1][ni], a[1], b0, b1);
            }
        }
        __syncthreads();
    }

    // epilogue
#pragma unroll
    for (int mi = 0; mi < 2; mi++) {
        int rg = row0 + wr * 32 + mi * 16 + qid;
#pragma unroll
        for (int ni = 0; ni < 8; ni++) {
            int cg = col0 + wc * 64 + ni * 8 + tig * 2;
            float bx = 0.0f, by = 0.0f;
            if (bias) { bx = bias[cg]; by = bias[cg + 1]; }
            float o0 = alpha * acc[mi][ni][0] + bx;
            float o1 = alpha * acc[mi][ni][1] + by;
            float o2 = alpha * acc[mi][ni][2] + bx;
            float o3 = alpha * acc[mi][ni][3] + by;
            if (CVTC) { o0 = f2tf(o0); o1 = f2tf(o1); o2 = f2tf(o2); o3 = f2tf(o3); }
            *reinterpret_cast<float2*>(C + (size_t)rg * ldc + cg)       = make_float2(o0, o1);
            *reinterpret_cast<float2*>(C + (size_t)(rg + 8) * ldc + cg) = make_float2(o2, o3);
        }
    }
}

// ============================================================================
// transpose: out[c][r] = in[r][c], dims multiples of 32, batched
// cvt: round output to tf32 (for GEMM operands)
// ============================================================================
__global__ __launch_bounds__(256)
void transpose_k(const float* __restrict__ in, float* __restrict__ out,
                 int ldi, int ldo,
                 long long siHi, long long siLo, long long soHi, long long soLo,
                 int zdiv, int cvt)
{
    int z = blockIdx.z;
    in  += (z / zdiv) * siHi + (z % zdiv) * siLo;
    out += (z / zdiv) * soHi + (z % zdiv) * soLo;
    __shared__ float t[32][33];
    int bx = blockIdx.x * 32, by = blockIdx.y * 32;
    int tx = threadIdx.x & 31, ty = threadIdx.x >> 5;
#pragma unroll
    for (int i = 0; i < 4; i++)
        t[ty + 8 * i][tx] = in[(size_t)(by + ty + 8 * i) * ldi + bx + tx];
    __syncthreads();
    if (cvt) {
#pragma unroll
        for (int i = 0; i < 4; i++)
            out[(size_t)(bx + ty + 8 * i) * ldo + by + tx] = f2tf(t[tx][ty + 8 * i]);
    } else {
#pragma unroll
        for (int i = 0; i < 4; i++)
            out[(size_t)(bx + ty + 8 * i) * ldo + by + tx] = t[tx][ty + 8 * i];
    }
}

// pack compact [4096,4992] -> [4096,5120] head layout, tf32-rounded
__global__ void pack_k(const float* __restrict__ src, float* __restrict__ dst)
{
    int idx = blockIdx.x * blockDim.x + threadIdx.x;   // float4 index
    if (idx >= MROWS * (NCOMP / 4)) return;
    int m = idx / (NCOMP / 4);
    int q = idx % (NCOMP / 4);
    int h = q / (SPLITD / 4);
    int j = q % (SPLITD / 4);
    float4 v = *reinterpret_cast<const float4*>(src + (size_t)m * NCOMP + q * 4);
    v.x = f2tf(v.x); v.y = f2tf(v.y); v.z = f2tf(v.z); v.w = f2tf(v.w);
    *reinterpret_cast<float4*>(dst + (size_t)m * DM + h * DH + j * 4) = v;
}

// ---------------- RoPE ----------------
// dst write (GEMM operand) tf32-rounded; rout (k_rot output) full precision
__global__ void rope_k(const float* __restrict__ rot, float* __restrict__ dst,
                       float* __restrict__ rout)
{
    int idx = blockIdx.x * blockDim.x + threadIdx.x;
    if (idx >= MROWS * DKV) return;
    int m = idx >> 7;
    int c = idx & 127;
    int h = c >> 4;
    int d = c & 15;
    int j = d & 7;
    int s = m & (SEQ - 1);
    float t = (float)s * (1.0f / 40.0f);
    float invf = __expf(-(float)j * 0.86346941f);  // ln(1000)/8
    float ang = t * invf;
    float sn, cs;
    sincosf(ang, &sn, &cs);
    float x = rot[idx];
    float p = rot[(m << 7) + (h << 4) + ((d < 8) ? d + 8 : d - 8)];
    float val = x * cs + ((d < 8) ? -p : p) * sn;
    dst[(size_t)m * DM + h * DH + SPLITD + d] = f2tf(val);
    if (rout) rout[idx] = val;
}

// ---------------- softmax over rows of length SEQ (tf32-rounded store) ----
__global__ __launch_bounds__(256) void softmax_k(float* __restrict__ s)
{
    float* row = s + (size_t)blockIdx.x * SEQ;
    int t = threadIdx.x;
    float v[8];
    float mx = -1e30f;
#pragma unroll
    for (int i = 0; i < 8; i++) { v[i] = row[t + i * 256]; mx = fmaxf(mx, v[i]); }
    __shared__ float red[256];
    red[t] = mx; __syncthreads();
    for (int off = 128; off > 0; off >>= 1) {
        if (t < off) red[t] = fmaxf(red[t], red[t + off]);
        __syncthreads();
    }
    mx = red[0]; __syncthreads();
    float sum = 0.0f;
#pragma unroll
    for (int i = 0; i < 8; i++) { v[i] = __expf(v[i] - mx); sum += v[i]; }
    red[t] = sum; __syncthreads();
    for (int off = 128; off > 0; off >>= 1) {
        if (t < off) red[t] += red[t + off];
        __syncthreads();
    }
    float inv = 1.0f / red[0];
#pragma unroll
    for (int i = 0; i < 8; i++) row[t + i * 256] = f2tf(v[i] * inv);
}

__global__ void copy_k(const float* __restrict__ src, float* __restrict__ dst, int n)
{
    int i = blockIdx.x * blockDim.x + threadIdx.x;
    if (i < n) dst[i] = src[i];
}

// ============================================================================
// host launcher
// ============================================================================
extern "C" void kernel_launch(void* const* d_in, const int* in_sizes, int n_in,
                              void* d_out, int out_size)
{
    const float* h    = (const float*)d_in[0];
    const float* Wdkv = (const float*)d_in[1];
    const float* bdkv = (const float*)d_in[2];
    const float* Wdq  = (const float*)d_in[3];
    const float* bdq  = (const float*)d_in[4];
    const float* Wuk  = (const float*)d_in[5];
    const float* buk  = (const float*)d_in[6];
    const float* Wuv  = (const float*)d_in[7];
    const float* buv  = (const float*)d_in[8];
    const float* Wuq  = (const float*)d_in[9];
    const float* buq  = (const float*)d_in[10];
    const float* Wqr  = (const float*)d_in[11];
    const float* bqr  = (const float*)d_in[12];
    const float* Wkr  = (const float*)d_in[13];
    const float* bkr  = (const float*)d_in[14];
    const float* outw = (const float*)d_in[15];
    const float* outb = (const float*)d_in[16];
    float* out = (float*)d_out;

    float *ckv, *cq, *qrot, *krot, *kbt, *qbt, *qb, *kb, *vb, *vt, *ao, *sc;
    float *wt_dkv, *wt_dq, *wt_uk, *wt_uq, *wt_uv, *wt_kr, *wt_qr, *wt_out;
    cudaGetSymbolAddress((void**)&ckv,  g_ckv);
    cudaGetSymbolAddress((void**)&cq,   g_cq);
    cudaGetSymbolAddress((void**)&qrot, g_qrot);
    cudaGetSymbolAddress((void**)&krot, g_krot);
    cudaGetSymbolAddress((void**)&kbt,  g_kbt);
    cudaGetSymbolAddress((void**)&qbt,  g_qbt);
    cudaGetSymbolAddress((void**)&qb,   g_q);
    cudaGetSymbolAddress((void**)&kb,   g_k);
    cudaGetSymbolAddress((void**)&vb,   g_v);
    cudaGetSymbolAddress((void**)&vt,   g_vt);
    cudaGetSymbolAddress((void**)&ao,   g_ao);
    cudaGetSymbolAddress((void**)&sc,   g_sc);
    cudaGetSymbolAddress((void**)&wt_dkv, g_wt_dkv);
    cudaGetSymbolAddress((void**)&wt_dq,  g_wt_dq);
    cudaGetSymbolAddress((void**)&wt_uk,  g_wt_uk);
    cudaGetSymbolAddress((void**)&wt_uq,  g_wt_uq);
    cudaGetSymbolAddress((void**)&wt_uv,  g_wt_uv);
    cudaGetSymbolAddress((void**)&wt_kr,  g_wt_kr);
    cudaGetSymbolAddress((void**)&wt_qr,  g_wt_qr);
    cudaGetSymbolAddress((void**)&wt_out, g_wt_out);

    dim3 b256(256);
    // ---- weight transposes, pre-rounded to tf32 ----
    transpose_k<<<dim3(DKV/32, DM/32, 1), b256>>>(Wdkv, wt_dkv, DKV, DM, 0,0,0,0, 1, 1);
    transpose_k<<<dim3(DKV/32, DM/32, 1), b256>>>(Wdq,  wt_dq,  DKV, DM, 0,0,0,0, 1, 1);
    transpose_k<<<dim3(NCOMP/32, DKV/32, 1), b256>>>(Wuk, wt_uk, NCOMP, DKV, 0,0,0,0, 1, 1);
    transpose_k<<<dim3(NCOMP/32, DKV/32, 1), b256>>>(Wuq, wt_uq, NCOMP, DKV, 0,0,0,0, 1, 1);
    transpose_k<<<dim3(DM/32, DKV/32, 1), b256>>>(Wuv, wt_uv, DM, DKV, 0,0,0,0, 1, 1);
    transpose_k<<<dim3(DKV/32, DKV/32, 1), b256>>>(Wkr, wt_kr, DKV, DKV, 0,0,0,0, 1, 1);
    transpose_k<<<dim3(DKV/32, DKV/32, 1), b256>>>(Wqr, wt_qr, DKV, DKV, 0,0,0,0, 1, 1);
    transpose_k<<<dim3(DM/32, DM/32, 1), b256>>>(outw, wt_out, DM, DM, 0,0,0,0, 1, 1);

    dim3 blk(256);
    auto grd = [](int M, int N, int Z) { return dim3((unsigned)(N / 128), (unsigned)(M / 128), (unsigned)Z); };

    // 1) down projections: A=h raw (CVTA), B pre-rounded.
    //    ckv is a model output -> keep full precision (CVTC=0).
    //    cq is internal -> round (CVTC=1) so its consumers skip CVTA.
    mmagemm<true,false,false><<<grd(MROWS, DKV, 1), blk>>>(h, wt_dkv, ckv, bdkv,
        MROWS, DKV, DM, DM, DM, DKV, 1.0f, 0,0,0,0,0,0, 1);
    mmagemm<true,false,true><<<grd(MROWS, DKV, 1), blk>>>(h, wt_dq, cq, bdq,
        MROWS, DKV, DM, DM, DM, DKV, 1.0f, 0,0,0,0,0,0, 1);

    // 2) up projections: ckv is full precision -> CVTA on its consumers; cq pre-rounded.
    mmagemm<true,false,false><<<grd(MROWS, NCOMP, 1), blk>>>(ckv, wt_uk, kbt, buk,
        MROWS, NCOMP, DKV, DKV, DKV, NCOMP, 1.0f, 0,0,0,0,0,0, 1);
    mmagemm<false,false,false><<<grd(MROWS, NCOMP, 1), blk>>>(cq, wt_uq, qbt, buq,
        MROWS, NCOMP, DKV, DKV, DKV, NCOMP, 1.0f, 0,0,0,0,0,0, 1);
    mmagemm<true,false,false><<<grd(MROWS, DM, 1), blk>>>(ckv, wt_uv, vb, buv,
        MROWS, DM, DKV, DKV, DKV, DM, 1.0f, 0,0,0,0,0,0, 1);
    mmagemm<true,false,false><<<grd(MROWS, DKV, 1), blk>>>(ckv, wt_kr, krot, bkr,
        MROWS, DKV, DKV, DKV, DKV, DKV, 1.0f, 0,0,0,0,0,0, 1);
    mmagemm<false,false,false><<<grd(MROWS, DKV, 1), blk>>>(cq, wt_qr, qrot, bqr,
        MROWS, DKV, DKV, DKV, DKV, DKV, 1.0f, 0,0,0,0,0,0, 1);

    // pack compact bases into [*,5120] head layout (tf32-rounded)
    pack_k<<<(MROWS * (NCOMP/4) + 255) / 256, 256>>>(kbt, kb);
    pack_k<<<(MROWS * (NCOMP/4) + 255) / 256, 256>>>(qbt, qb);

    // 3) RoPE + secondary outputs
    const size_t out_ckv_off  = (size_t)MROWS * DM;
    const size_t out_krot_off = out_ckv_off + (size_t)MROWS * DKV;
    bool full_out = (size_t)out_size >= out_krot_off + (size_t)MROWS * DKV;

    rope_k<<<(MROWS * DKV + 255) / 256, 256>>>(qrot, qb, nullptr);
    rope_k<<<(MROWS * DKV + 255) / 256, 256>>>(krot, kb,
        full_out ? (out + out_krot_off) : nullptr);
    if (full_out)
        copy_k<<<(MROWS * DKV + 255) / 256, 256>>>(ckv, out + out_ckv_off, MROWS * DKV);

    // V transpose per (b,h): [2048,640] -> [640,2048], tf32-rounded
    const long long SDM = (long long)SEQ * DM;
    const long long HDS = (long long)DH * SEQ;
    transpose_k<<<dim3(DH/32, SEQ/32, BATCH*NH), b256>>>(vb, vt, DM, SEQ,
        SDM, DH, (long long)NH * HDS, HDS, NH, 1);

    // 4) attention scores: q/k pre-rounded -> no cvt in loop
    const long long SS = (long long)SEQ * SEQ;
    float inv_sqrt = 1.0f / sqrtf((float)DH);
    mmagemm<false,false,false><<<grd(SEQ, SEQ, BATCH*NH), blk>>>(qb, kb, sc, nullptr,
        SEQ, SEQ, DH, DM, DM, SEQ, inv_sqrt,
        SDM, DH, SDM, DH, (long long)NH * SS, SS, NH);

    // 5) softmax (rounds probs to tf32 on store)
    softmax_k<<<BATCH * NH * SEQ, 256>>>(sc);

    // 6) attn @ v : both operands pre-rounded; round ao for outproj
    mmagemm<false,false,true><<<grd(SEQ, DH, BATCH*NH), blk>>>(sc, vt, ao, nullptr,
        SEQ, DH, SEQ, SEQ, SEQ, DM, 1.0f,
        (long long)NH * SS, SS, (long long)NH * HDS, HDS, SDM, DH, NH);

    // 7) output projection: everything pre-rounded
    mmagemm<false,false,false><<<grd(MROWS, DM, 1), blk>>>(ao, wt_out, out, outb,
        MROWS, DM, DM, DM, DM, DM, 1.0f, 0,0,0,0,0,0, 1);
}

// round 5
// speedup vs baseline: 2.0206x; 2.0206x over previous
#include <cuda_runtime.h>
#include <cuda_fp16.h>
#include <math.h>
#include <stdint.h>

// ---------------- problem constants ----------------
#define BATCH 2
#define SEQ   2048
#define DM    5120
#define NH    8
#define DH    640
#define DR    16
#define SPLITD 624
#define DKV   128
#define MROWS (BATCH*SEQ)        // 4096
#define NCOMP (NH*SPLITD)        // 4992 = 39*128

// ---------------- scratch (device globals; no allocs allowed) ----------------
__device__ __align__(16) __half g_hh  [(size_t)MROWS*DM];     // h in half
__device__ __align__(16) __half g_ckvh[MROWS*DKV];
__device__ __align__(16) __half g_cqh [MROWS*DKV];
__device__ __align__(16) __half g_qroth[MROWS*DKV];
__device__ __align__(16) __half g_kroth[MROWS*DKV];
__device__ __align__(16) __half g_kbt [(size_t)MROWS*NCOMP];
__device__ __align__(16) __half g_qbt [(size_t)MROWS*NCOMP];
__device__ __align__(16) __half g_q   [(size_t)MROWS*DM];
__device__ __align__(16) __half g_k   [(size_t)MROWS*DM];
__device__ __align__(16) __half g_v   [(size_t)MROWS*DM];
__device__ __align__(16) __half g_vt  [(size_t)MROWS*DM];
__device__ __align__(16) __half g_ao  [(size_t)MROWS*DM];
__device__ __align__(16) __half g_sc  [(size_t)BATCH*NH*SEQ*SEQ];   // 128 MB
__device__ __align__(16) float  g_ckvf[MROWS*DKV];                   // ckv float (when not in out)
// transposed weights, half
__device__ __align__(16) __half g_wt_dkv[DKV*DM];
__device__ __align__(16) __half g_wt_dq [DKV*DM];
__device__ __align__(16) __half g_wt_uk [NCOMP*DKV];
__device__ __align__(16) __half g_wt_uq [NCOMP*DKV];
__device__ __align__(16) __half g_wt_uv [DM*DKV];
__device__ __align__(16) __half g_wt_kr [DKV*DKV];
__device__ __align__(16) __half g_wt_qr [DKV*DKV];
__device__ __align__(16) __half g_wt_out[(size_t)DM*DM];

// ---------------- PTX helpers ----------------
__device__ __forceinline__ uint32_t smem_u32(const void* p) {
    uint32_t a;
    asm("{ .reg .u64 t; cvta.to.shared.u64 t, %1; cvt.u32.u64 %0, t; }" : "=r"(a) : "l"(p));
    return a;
}
__device__ __forceinline__ void cp16(uint32_t dst, const void* src) {
    asm volatile("cp.async.cg.shared.global [%0], [%1], 16;" :: "r"(dst), "l"(src) : "memory");
}
#define CP_COMMIT() asm volatile("cp.async.commit_group;" ::: "memory")
#define CP_WAIT(n)  asm volatile("cp.async.wait_group %0;" :: "n"(n) : "memory")

__device__ __forceinline__ void ldm_x4(uint32_t* r, uint32_t addr) {
    asm volatile("ldmatrix.sync.aligned.m8n8.x4.shared.b16 {%0,%1,%2,%3}, [%4];"
                 : "=r"(r[0]), "=r"(r[1]), "=r"(r[2]), "=r"(r[3]) : "r"(addr));
}
__device__ __forceinline__ void mma_f16(float* c, const uint32_t* a, uint32_t b0, uint32_t b1) {
    asm volatile("mma.sync.aligned.m16n8k16.row.col.f32.f16.f16.f32 "
                 "{%0,%1,%2,%3}, {%4,%5,%6,%7}, {%8,%9}, {%0,%1,%2,%3};"
                 : "+f"(c[0]), "+f"(c[1]), "+f"(c[2]), "+f"(c[3])
                 : "r"(a[0]), "r"(a[1]), "r"(a[2]), "r"(a[3]), "r"(b0), "r"(b1));
}

// ============================================================================
// fp16 mma.sync GEMM: C[M,N] = alpha * A[M,K] * B[N,K]^T (+ bias)
// A,B half; C -> optional float (Cf) and/or half (Ch) outputs, fp32 accumulate
// M%128==0, N%128==0, K%32==0. 256 threads, CTA tile 128x128, BK=32.
// ============================================================================
#define SPADH 40   // 32 + 8 halfs pad (80B rows: conflict-free for ldmatrix)

__global__ __launch_bounds__(256)
void hgemm(const __half* __restrict__ A, const __half* __restrict__ B,
           float* __restrict__ Cf, __half* __restrict__ Ch,
           const float* __restrict__ bias,
           int M, int N, int K, int lda, int ldb, int ldc, float alpha,
           long long sAhi, long long sAlo, long long sBhi, long long sBlo,
           long long sChi, long long sClo, int zdiv)
{
    __shared__ __half As[2][128][SPADH];
    __shared__ __half Bs[2][128][SPADH];

    int tid  = threadIdx.x;
    int warp = tid >> 5;
    int lane = tid & 31;
    int wr = warp >> 1;          // 0..3
    int wc = warp & 1;           // 0..1
    int qid = lane >> 2;         // 0..7
    int tig = lane & 3;          // 0..3

    int z  = blockIdx.z;
    int zh = z / zdiv, zl = z % zdiv;
    A += zh * sAhi + zl * sAlo;
    B += zh * sBhi + zl * sBlo;
    long long cofs = zh * sChi + zl * sClo;
    if (Cf) Cf += cofs;
    if (Ch) Ch += cofs;

    int row0 = blockIdx.y * 128, col0 = blockIdx.x * 128;
    const __half* Ab = A + (size_t)row0 * lda;
    const __half* Bb = B + (size_t)col0 * ldb;

    // cp.async coords: 512 chunks (8 halfs) per operand per tile, 2 per thread
    int r0 = tid >> 2, cc = (tid & 3) * 8;
    int r1 = r0 + 64;
    uint32_t dA0[2], dA1[2], dB0[2], dB1[2];
#pragma unroll
    for (int s = 0; s < 2; s++) {
        dA0[s] = smem_u32(&As[s][r0][cc]);
        dA1[s] = smem_u32(&As[s][r1][cc]);
        dB0[s] = smem_u32(&Bs[s][r0][cc]);
        dB1[s] = smem_u32(&Bs[s][r1][cc]);
    }
    // ldmatrix base addresses (ks=0)
    uint32_t aAddr[2][2], bAddr[2][4];
#pragma unroll
    for (int s = 0; s < 2; s++) {
#pragma unroll
        for (int mi = 0; mi < 2; mi++)
            aAddr[s][mi] = smem_u32(&As[s][wr * 32 + mi * 16 + (lane & 15)][(lane >> 4) * 8]);
#pragma unroll
        for (int np = 0; np < 4; np++)
            bAddr[s][np] = smem_u32(&Bs[s][wc * 64 + np * 16 + (lane & 7) + ((lane >> 4) & 1) * 8]
                                        [((lane >> 3) & 1) * 8]);
    }

    float acc[2][8][4];
#pragma unroll
    for (int mi = 0; mi < 2; mi++)
#pragma unroll
        for (int ni = 0; ni < 8; ni++)
#pragma unroll
            for (int i = 0; i < 4; i++) acc[mi][ni][i] = 0.0f;

    int T = K >> 5;   // BK = 32

    // prologue: tile 0
    cp16(dA0[0], Ab + (size_t)r0 * lda + cc);
    cp16(dA1[0], Ab + (size_t)r1 * lda + cc);
    cp16(dB0[0], Bb + (size_t)r0 * ldb + cc);
    cp16(dB1[0], Bb + (size_t)r1 * ldb + cc);
    CP_COMMIT();

    for (int t = 0; t < T; t++) {
        if (t + 1 < T) {
            int s = (t + 1) & 1;
            int k0 = (t + 1) * 32;
            cp16(dA0[s], Ab + (size_t)r0 * lda + k0 + cc);
            cp16(dA1[s], Ab + (size_t)r1 * lda + k0 + cc);
            cp16(dB0[s], Bb + (size_t)r0 * ldb + k0 + cc);
            cp16(dB1[s], Bb + (size_t)r1 * ldb + k0 + cc);
            CP_COMMIT();
            CP_WAIT(1);
        } else {
            CP_WAIT(0);
        }
        __syncthreads();

        int s = t & 1;
#pragma unroll
        for (int ks = 0; ks < 2; ks++) {
            uint32_t koff = ks * 32;  // 16 halfs = 32 bytes
            uint32_t a[2][4], b[16];
#pragma unroll
            for (int mi = 0; mi < 2; mi++) ldm_x4(a[mi], aAddr[s][mi] + koff);
#pragma unroll
            for (int np = 0; np < 4; np++) ldm_x4(b + np * 4, bAddr[s][np] + koff);
#pragma unroll
            for (int ni = 0; ni < 8; ni++) {
                uint32_t b0 = b[(ni >> 1) * 4 + (ni & 1) * 2];
                uint32_t b1 = b[(ni >> 1) * 4 + (ni & 1) * 2 + 1];
                mma_f16(acc[0][ni], a[0], b0, b1);
                mma_f16(acc[1][ni], a[1], b0, b1);
            }
        }
        __syncthreads();
    }

    // epilogue
#pragma unroll
    for (int mi = 0; mi < 2; mi++) {
        int rg = row0 + wr * 32 + mi * 16 + qid;
#pragma unroll
        for (int ni = 0; ni < 8; ni++) {
            int cg = col0 + wc * 64 + ni * 8 + tig * 2;
            float bx = 0.0f, by = 0.0f;
            if (bias) { bx = bias[cg]; by = bias[cg + 1]; }
            float o0 = alpha * acc[mi][ni][0] + bx;
            float o1 = alpha * acc[mi][ni][1] + by;
            float o2 = alpha * acc[mi][ni][2] + bx;
            float o3 = alpha * acc[mi][ni][3] + by;
            if (Cf) {
                *reinterpret_cast<float2*>(Cf + (size_t)rg * ldc + cg)       = make_float2(o0, o1);
                *reinterpret_cast<float2*>(Cf + (size_t)(rg + 8) * ldc + cg) = make_float2(o2, o3);
            }
            if (Ch) {
                *reinterpret_cast<__half2*>(Ch + (size_t)rg * ldc + cg)       = __floats2half2_rn(o0, o1);
                *reinterpret_cast<__half2*>(Ch + (size_t)(rg + 8) * ldc + cg) = __floats2half2_rn(o2, o3);
            }
        }
    }
}

// ============================================================================
// transposes
// ============================================================================
__global__ __launch_bounds__(256)
void transpose_f2h(const float* __restrict__ in, __half* __restrict__ out, int ldi, int ldo)
{
    __shared__ float t[32][33];
    int bx = blockIdx.x * 32, by = blockIdx.y * 32;
    int tx = threadIdx.x & 31, ty = threadIdx.x >> 5;
#pragma unroll
    for (int i = 0; i < 4; i++)
        t[ty + 8 * i][tx] = in[(size_t)(by + ty + 8 * i) * ldi + bx + tx];
    __syncthreads();
#pragma unroll
    for (int i = 0; i < 4; i++)
        out[(size_t)(bx + ty + 8 * i) * ldo + by + tx] = __float2half_rn(t[tx][ty + 8 * i]);
}

__global__ __launch_bounds__(256)
void transpose_h2h(const __half* __restrict__ in, __half* __restrict__ out,
                   int ldi, int ldo,
                   long long siHi, long long siLo, long long soHi, long long soLo, int zdiv)
{
    int z = blockIdx.z;
    in  += (z / zdiv) * siHi + (z % zdiv) * siLo;
    out += (z / zdiv) * soHi + (z % zdiv) * soLo;
    __shared__ __half t[32][34];
    int bx = blockIdx.x * 32, by = blockIdx.y * 32;
    int tx = threadIdx.x & 31, ty = threadIdx.x >> 5;
#pragma unroll
    for (int i = 0; i < 4; i++)
        t[ty + 8 * i][tx] = in[(size_t)(by + ty + 8 * i) * ldi + bx + tx];
    __syncthreads();
#pragma unroll
    for (int i = 0; i < 4; i++)
        out[(size_t)(bx + ty + 8 * i) * ldo + by + tx] = t[tx][ty + 8 * i];
}

// float -> half convert
__global__ void f2h_k(const float* __restrict__ in, __half* __restrict__ out, int n4)
{
    int i = blockIdx.x * blockDim.x + threadIdx.x;
    if (i >= n4) return;
    float4 v = *reinterpret_cast<const float4*>(in + (size_t)i * 4);
    __half2 a = __floats2half2_rn(v.x, v.y);
    __half2 b = __floats2half2_rn(v.z, v.w);
    *reinterpret_cast<uint2*>(out + (size_t)i * 4) = make_uint2(
        *reinterpret_cast<uint32_t*>(&a), *reinterpret_cast<uint32_t*>(&b));
}

// pack compact [4096,4992] -> [4096,5120] head layout (half, 16B chunks)
__global__ void pack_k(const __half* __restrict__ src, __half* __restrict__ dst)
{
    int idx = blockIdx.x * blockDim.x + threadIdx.x;   // 8-half chunk index
    if (idx >= MROWS * (NCOMP / 8)) return;
    int m = idx / (NCOMP / 8);
    int q = idx % (NCOMP / 8);
    int h = q / (SPLITD / 8);
    int j = q % (SPLITD / 8);
    uint4 v = *reinterpret_cast<const uint4*>(src + (size_t)m * NCOMP + q * 8);
    *reinterpret_cast<uint4*>(dst + (size_t)m * DM + h * DH + j * 8) = v;
}

// ---------------- RoPE (half in, half into q/k, float k_rot out) ----------------
__global__ void rope_k(const __half* __restrict__ rot, __half* __restrict__ dst,
                       float* __restrict__ rout)
{
    int idx = blockIdx.x * blockDim.x + threadIdx.x;
    if (idx >= MROWS * DKV) return;
    int m = idx >> 7;
    int c = idx & 127;
    int h = c >> 4;
    int d = c & 15;
    int j = d & 7;
    int s = m & (SEQ - 1);
    float t = (float)s * (1.0f / 40.0f);
    float invf = __expf(-(float)j * 0.86346941f);  // ln(1000)/8
    float ang = t * invf;
    float sn, cs;
    sincosf(ang, &sn, &cs);
    float x = __half2float(rot[idx]);
    float p = __half2float(rot[(m << 7) + (h << 4) + ((d < 8) ? d + 8 : d - 8)]);
    float val = x * cs + ((d < 8) ? -p : p) * sn;
    dst[(size_t)m * DM + h * DH + SPLITD + d] = __float2half_rn(val);
    if (rout) rout[idx] = val;
}

// ---------------- softmax over rows of length SEQ (half) ----------------
__global__ __launch_bounds__(256) void softmax_k(__half* __restrict__ s)
{
    __half2* row = reinterpret_cast<__half2*>(s + (size_t)blockIdx.x * SEQ);
    int t = threadIdx.x;
    float v[8];
    float mx = -1e30f;
#pragma unroll
    for (int i = 0; i < 4; i++) {
        float2 f = __half22float2(row[t + i * 256]);
        v[2 * i] = f.x; v[2 * i + 1] = f.y;
        mx = fmaxf(mx, fmaxf(f.x, f.y));
    }
    __shared__ float red[256];
    red[t] = mx; __syncthreads();
    for (int off = 128; off > 0; off >>= 1) {
        if (t < off) red[t] = fmaxf(red[t], red[t + off]);
        __syncthreads();
    }
    mx = red[0]; __syncthreads();
    float sum = 0.0f;
#pragma unroll
    for (int i = 0; i < 8; i++) { v[i] = __expf(v[i] - mx); sum += v[i]; }
    red[t] = sum; __syncthreads();
    for (int off = 128; off > 0; off >>= 1) {
        if (t < off) red[t] += red[t + off];
        __syncthreads();
    }
    float inv = 1.0f / red[0];
#pragma unroll
    for (int i = 0; i < 4; i++)
        row[t + i * 256] = __floats2half2_rn(v[2 * i] * inv, v[2 * i + 1] * inv);
}

// ============================================================================
// host launcher
// ============================================================================
extern "C" void kernel_launch(void* const* d_in, const int* in_sizes, int n_in,
                              void* d_out, int out_size)
{
    const float* h    = (const float*)d_in[0];
    const float* Wdkv = (const float*)d_in[1];
    const float* bdkv = (const float*)d_in[2];
    const float* Wdq  = (const float*)d_in[3];
    const float* bdq  = (const float*)d_in[4];
    const float* Wuk  = (const float*)d_in[5];
    const float* buk  = (const float*)d_in[6];
    const float* Wuv  = (const float*)d_in[7];
    const float* buv  = (const float*)d_in[8];
    const float* Wuq  = (const float*)d_in[9];
    const float* buq  = (const float*)d_in[10];
    const float* Wqr  = (const float*)d_in[11];
    const float* bqr  = (const float*)d_in[12];
    const float* Wkr  = (const float*)d_in[13];
    const float* bkr  = (const float*)d_in[14];
    const float* outw = (const float*)d_in[15];
    const float* outb = (const float*)d_in[16];
    float* out = (float*)d_out;

    __half *hh, *ckvh, *cqh, *qroth, *kroth, *kbt, *qbt, *qb, *kb, *vb, *vt, *ao, *sc;
    __half *wt_dkv, *wt_dq, *wt_uk, *wt_uq, *wt_uv, *wt_kr, *wt_qr, *wt_out;
    float *ckvf;
    cudaGetSymbolAddress((void**)&hh,    g_hh);
    cudaGetSymbolAddress((void**)&ckvh,  g_ckvh);
    cudaGetSymbolAddress((void**)&cqh,   g_cqh);
    cudaGetSymbolAddress((void**)&qroth, g_qroth);
    cudaGetSymbolAddress((void**)&kroth, g_kroth);
    cudaGetSymbolAddress((void**)&kbt,   g_kbt);
    cudaGetSymbolAddress((void**)&qbt,   g_qbt);
    cudaGetSymbolAddress((void**)&qb,    g_q);
    cudaGetSymbolAddress((void**)&kb,    g_k);
    cudaGetSymbolAddress((void**)&vb,    g_v);
    cudaGetSymbolAddress((void**)&vt,    g_vt);
    cudaGetSymbolAddress((void**)&ao,    g_ao);
    cudaGetSymbolAddress((void**)&sc,    g_sc);
    cudaGetSymbolAddress((void**)&ckvf,  g_ckvf);
    cudaGetSymbolAddress((void**)&wt_dkv, g_wt_dkv);
    cudaGetSymbolAddress((void**)&wt_dq,  g_wt_dq);
    cudaGetSymbolAddress((void**)&wt_uk,  g_wt_uk);
    cudaGetSymbolAddress((void**)&wt_uq,  g_wt_uq);
    cudaGetSymbolAddress((void**)&wt_uv,  g_wt_uv);
    cudaGetSymbolAddress((void**)&wt_kr,  g_wt_kr);
    cudaGetSymbolAddress((void**)&wt_qr,  g_wt_qr);
    cudaGetSymbolAddress((void**)&wt_out, g_wt_out);

    dim3 b256(256);
    // ---- input conversion + weight transposes (float -> half, [N,K]) ----
    f2h_k<<<((size_t)MROWS * DM / 4 + 255) / 256, 256>>>(h, hh, MROWS * DM / 4);
    transpose_f2h<<<dim3(DKV/32, DM/32), b256>>>(Wdkv, wt_dkv, DKV, DM);
    transpose_f2h<<<dim3(DKV/32, DM/32), b256>>>(Wdq,  wt_dq,  DKV, DM);
    transpose_f2h<<<dim3(NCOMP/32, DKV/32), b256>>>(Wuk, wt_uk, NCOMP, DKV);
    transpose_f2h<<<dim3(NCOMP/32, DKV/32), b256>>>(Wuq, wt_uq, NCOMP, DKV);
    transpose_f2h<<<dim3(DM/32, DKV/32), b256>>>(Wuv, wt_uv, DM, DKV);
    transpose_f2h<<<dim3(DKV/32, DKV/32), b256>>>(Wkr, wt_kr, DKV, DKV);
    transpose_f2h<<<dim3(DKV/32, DKV/32), b256>>>(Wqr, wt_qr, DKV, DKV);
    transpose_f2h<<<dim3(DM/32, DM/32), b256>>>(outw, wt_out, DM, DM);

    const size_t out_ckv_off  = (size_t)MROWS * DM;
    const size_t out_krot_off = out_ckv_off + (size_t)MROWS * DKV;
    bool full_out = (size_t)out_size >= out_krot_off + (size_t)MROWS * DKV;
    float* ckv_dst = full_out ? (out + out_ckv_off) : ckvf;

    dim3 blk(256);
    auto grd = [](int M, int N, int Z) { return dim3((unsigned)(N / 128), (unsigned)(M / 128), (unsigned)Z); };

    // 1) down projections (ckv: float model-output + half for consumers)
    hgemm<<<grd(MROWS, DKV, 1), blk>>>(hh, wt_dkv, ckv_dst, ckvh, bdkv,
        MROWS, DKV, DM, DM, DM, DKV, 1.0f, 0,0,0,0,0,0, 1);
    hgemm<<<grd(MROWS, DKV, 1), blk>>>(hh, wt_dq, nullptr, cqh, bdq,
        MROWS, DKV, DM, DM, DM, DKV, 1.0f, 0,0,0,0,0,0, 1);

    // 2) up projections
    hgemm<<<grd(MROWS, NCOMP, 1), blk>>>(ckvh, wt_uk, nullptr, kbt, buk,
        MROWS, NCOMP, DKV, DKV, DKV, NCOMP, 1.0f, 0,0,0,0,0,0, 1);
    hgemm<<<grd(MROWS, NCOMP, 1), blk>>>(cqh, wt_uq, nullptr, qbt, buq,
        MROWS, NCOMP, DKV, DKV, DKV, NCOMP, 1.0f, 0,0,0,0,0,0, 1);
    hgemm<<<grd(MROWS, DM, 1), blk>>>(ckvh, wt_uv, nullptr, vb, buv,
        MROWS, DM, DKV, DKV, DKV, DM, 1.0f, 0,0,0,0,0,0, 1);
    hgemm<<<grd(MROWS, DKV, 1), blk>>>(ckvh, wt_kr, nullptr, kroth, bkr,
        MROWS, DKV, DKV, DKV, DKV, DKV, 1.0f, 0,0,0,0,0,0, 1);
    hgemm<<<grd(MROWS, DKV, 1), blk>>>(cqh, wt_qr, nullptr, qroth, bqr,
        MROWS, DKV, DKV, DKV, DKV, DKV, 1.0f, 0,0,0,0,0,0, 1);

    // pack compact bases into [*,5120] head layout
    pack_k<<<(MROWS * (NCOMP/8) + 255) / 256, 256>>>(kbt, kb);
    pack_k<<<(MROWS * (NCOMP/8) + 255) / 256, 256>>>(qbt, qb);

    // 3) RoPE (+ float k_rot output)
    rope_k<<<(MROWS * DKV + 255) / 256, 256>>>(qroth, qb, nullptr);
    rope_k<<<(MROWS * DKV + 255) / 256, 256>>>(kroth, kb,
        full_out ? (out + out_krot_off) : nullptr);

    // V transpose per (b,h): [2048,640] -> [640,2048]
    const long long SDM = (long long)SEQ * DM;
    const long long HDS = (long long)DH * SEQ;
    transpose_h2h<<<dim3(DH/32, SEQ/32, BATCH*NH), b256>>>(vb, vt, DM, SEQ,
        SDM, DH, (long long)NH * HDS, HDS, NH);

    // 4) attention scores: z = b*8+h
    const long long SS = (long long)SEQ * SEQ;
    float inv_sqrt = 1.0f / sqrtf((float)DH);
    hgemm<<<grd(SEQ, SEQ, BATCH*NH), blk>>>(qb, kb, nullptr, sc, nullptr,
        SEQ, SEQ, DH, DM, DM, SEQ, inv_sqrt,
        SDM, DH, SDM, DH, (long long)NH * SS, SS, NH);

    // 5) softmax
    softmax_k<<<BATCH * NH * SEQ, 256>>>(sc);

    // 6) attn @ v
    hgemm<<<grd(SEQ, DH, BATCH*NH), blk>>>(sc, vt, nullptr, ao, nullptr,
        SEQ, DH, SEQ, SEQ, SEQ, DM, 1.0f,
        (long long)NH * SS, SS, (long long)NH * HDS, HDS, SDM, DH, NH);

    // 7) output projection -> float out
    hgemm<<<grd(MROWS, DM, 1), blk>>>(ao, wt_out, out, nullptr, outb,
        MROWS, DM, DM, DM, DM, DM, 1.0f, 0,0,0,0,0,0, 1);
}